// round 2
// baseline (speedup 1.0000x reference)
#include <cuda_runtime.h>

#define BATCH 16
#define HH 128
#define WW 128
#define C4 32   // 128 channels as float4 groups

__device__ __forceinline__ float4 mix4(float4 a, float4 b, float wa, float wb) {
    float4 r;
    r.x = fmaf(wa, a.x, wb * b.x);
    r.y = fmaf(wa, a.y, wb * b.y);
    r.z = fmaf(wa, a.z, wb * b.z);
    r.w = fmaf(wa, a.w, wb * b.w);
    return r;
}

__device__ __forceinline__ float lrelu(float u) {
    return fmaxf(u, 0.01f * u);   // FMUL + FMNMX, no branch
}

__device__ __forceinline__ float4 lrelu4(float4 u) {
    float4 r;
    r.x = lrelu(u.x); r.y = lrelu(u.y); r.z = lrelu(u.z); r.w = lrelu(u.w);
    return r;
}

__device__ __forceinline__ float4 out4(const float4& u00, const float4& u01,
                                       const float4& u10, const float4& u11) {
    float4 a = lrelu4(u00), b = lrelu4(u01), c = lrelu4(u10), d = lrelu4(u11);
    float4 s;
    s.x = 0.25f * ((a.x + b.x) + (c.x + d.x));
    s.y = 0.25f * ((a.y + b.y) + (c.y + d.y));
    s.z = 0.25f * ((a.z + b.z) + (c.z + d.z));
    s.w = 0.25f * ((a.w + b.w) + (c.w + d.w));
    return s;
}

// Each thread: one float4 channel group, 4 consecutive output columns.
// block = (32 c4-lanes, 4 col-groups) = 128 threads
// grid  = (8, 128, 16)
__global__ __launch_bounds__(128)
void act_filter_kernel(const float4* __restrict__ X, float4* __restrict__ O) {
    const int c4 = threadIdx.x;                           // 0..31
    const int jg = blockIdx.x * 4 + threadIdx.y;          // 0..31
    const int j0 = jg * 4;
    const int i  = blockIdx.y;
    const int b  = blockIdx.z;

    // base pointer at (b, i, j0, c4)
    const size_t cidx = ((size_t)(b * HH + i) * WW + j0) * C4 + c4;
    const float4* __restrict__ base = X + cidx;
    float4* __restrict__ obase = O + cidx;

    float4 vp[6], vq[6];

    if (i > 0 && i < HH - 1 && jg > 0 && jg < (WW / 4) - 1) {
        // ---------------- interior fast path: all offsets compile-time ----------------
#pragma unroll
        for (int t = 0; t < 6; t++) {
            const int dc = (t - 1) * C4;
            float4 am = base[dc - WW * C4];
            float4 a0 = base[dc];
            float4 ap = base[dc + WW * C4];
            vp[t] = mix4(am, a0, 0.25f, 0.75f);
            vq[t] = mix4(ap, a0, 0.25f, 0.75f);
        }
    } else {
        // ---------------- boundary path: clamped indices ----------------
        const int im = (i > 0) ? i - 1 : 0;
        const int ip = (i < HH - 1) ? i + 1 : HH - 1;
        const size_t rowm = (size_t)(b * HH + im) * WW;
        const size_t row0 = (size_t)(b * HH + i ) * WW;
        const size_t rowp = (size_t)(b * HH + ip) * WW;

        int cols[6];
        cols[0] = (j0 > 0) ? j0 - 1 : 0;
        cols[1] = j0;  cols[2] = j0 + 1;  cols[3] = j0 + 2;  cols[4] = j0 + 3;
        cols[5] = (j0 + 4 < WW) ? j0 + 4 : WW - 1;

#pragma unroll
        for (int t = 0; t < 6; t++) {
            float4 am = X[(rowm + cols[t]) * C4 + c4];
            float4 a0 = X[(row0 + cols[t]) * C4 + c4];
            float4 ap = X[(rowp + cols[t]) * C4 + c4];
            vp[t] = mix4(am, a0, 0.25f, 0.75f);
            vq[t] = mix4(ap, a0, 0.25f, 0.75f);
        }
    }

#pragma unroll
    for (int jj = 0; jj < 4; jj++) {
        const int t = jj + 1;
        float4 u00 = mix4(vp[t - 1], vp[t], 0.25f, 0.75f);
        float4 u01 = mix4(vp[t + 1], vp[t], 0.25f, 0.75f);
        float4 u10 = mix4(vq[t - 1], vq[t], 0.25f, 0.75f);
        float4 u11 = mix4(vq[t + 1], vq[t], 0.25f, 0.75f);
        obase[jj * C4] = out4(u00, u01, u10, u11);
    }
}

extern "C" void kernel_launch(void* const* d_in, const int* in_sizes, int n_in,
                              void* d_out, int out_size) {
    const float4* X = (const float4*)d_in[0];
    float4* O = (float4*)d_out;
    dim3 block(32, 4, 1);
    dim3 grid(WW / 16, HH, BATCH);  // 8, 128, 16
    act_filter_kernel<<<grid, block>>>(X, O);
}

// round 3
// speedup vs baseline: 1.0243x; 1.0243x over previous
#include <cuda_runtime.h>

typedef unsigned long long ull;

#define BATCH 16
#define HH 128
#define WW 128
#define C4 32   // 128 channels as float4/ulonglong2 groups

// ---- packed fp32x2 primitives (sm_103a) ----
__device__ __forceinline__ ull mulp(ull a, ull b) {
    ull r; asm("mul.rn.f32x2 %0, %1, %2;" : "=l"(r) : "l"(a), "l"(b)); return r;
}
__device__ __forceinline__ ull addp(ull a, ull b) {
    ull r; asm("add.rn.f32x2 %0, %1, %2;" : "=l"(r) : "l"(a), "l"(b)); return r;
}
__device__ __forceinline__ ull fmap(ull a, ull b, ull c) {
    ull r; asm("fma.rn.f32x2 %0, %1, %2, %3;" : "=l"(r) : "l"(a), "l"(b), "l"(c)); return r;
}

#define W25 0x3E8000003E800000ULL   // {0.25f, 0.25f}
#define W75 0x3F4000003F400000ULL   // {0.75f, 0.75f}
#define W01 0x3C23D70A3C23D70AULL   // {0.01f, 0.01f}

struct V4 { ull a, b; };  // 4 packed floats

__device__ __forceinline__ V4 mix4p(const V4& x, const V4& y) {
    // 0.25*x + 0.75*y
    V4 r;
    r.a = fmap(x.a, W25, mulp(y.a, W75));
    r.b = fmap(x.b, W25, mulp(y.b, W75));
    return r;
}

__device__ __forceinline__ ull lrelup(ull u) {
    // per-lane max(u, 0.01u)
    ull t = mulp(u, W01);
    float u0, u1, t0, t1;
    asm("mov.b64 {%0,%1}, %2;" : "=f"(u0), "=f"(u1) : "l"(u));
    asm("mov.b64 {%0,%1}, %2;" : "=f"(t0), "=f"(t1) : "l"(t));
    u0 = fmaxf(u0, t0);
    u1 = fmaxf(u1, t1);
    ull r; asm("mov.b64 %0, {%1,%2};" : "=l"(r) : "f"(u0), "f"(u1));
    return r;
}

__device__ __forceinline__ ull sum4s(ull a, ull b, ull c, ull d) {
    // 0.25 * (lrelu(a)+lrelu(b)+lrelu(c)+lrelu(d))
    ull s = addp(addp(lrelup(a), lrelup(b)), addp(lrelup(c), lrelup(d)));
    return mulp(s, W25);
}

__device__ __forceinline__ V4 ldv(const ulonglong2* __restrict__ p) {
    ulonglong2 v = *p;
    V4 r; r.a = v.x; r.b = v.y;
    return r;
}

// Each thread: one 4-channel group, 4 consecutive output columns.
// block = (32 c4-lanes, 4 col-groups) = 128 threads; grid = (8, 128, 16)
__global__ __launch_bounds__(128)
void act_filter_kernel(const ulonglong2* __restrict__ X, ulonglong2* __restrict__ O) {
    const int c4 = threadIdx.x;                    // 0..31
    const int jg = blockIdx.x * 4 + threadIdx.y;   // 0..31
    const int j0 = jg * 4;
    const int i  = blockIdx.y;
    const int b  = blockIdx.z;

    const int cidx = ((b * HH + i) * WW + j0) * C4 + c4;   // fits in 32 bits
    const ulonglong2* __restrict__ base = X + cidx;
    ulonglong2* __restrict__ obase = O + cidx;

    V4 vp[6], vq[6];

    if (i > 0 && i < HH - 1 && jg > 0 && jg < (WW / 4) - 1) {
        // interior: all load offsets are compile-time immediates
#pragma unroll
        for (int t = 0; t < 6; t++) {
            const int dc = (t - 1) * C4;
            V4 am = ldv(base + (dc - WW * C4));
            V4 a0 = ldv(base + dc);
            V4 ap = ldv(base + (dc + WW * C4));
            vp[t] = mix4p(am, a0);
            vq[t] = mix4p(ap, a0);
        }
    } else {
        // boundary: clamped indices, 32-bit math
        const int im = (i > 0) ? i - 1 : 0;
        const int ip = (i < HH - 1) ? i + 1 : HH - 1;
        const int rowm = (b * HH + im) * WW;
        const int row0 = (b * HH + i ) * WW;
        const int rowp = (b * HH + ip) * WW;

        int cols[6];
        cols[0] = (j0 > 0) ? j0 - 1 : 0;
        cols[1] = j0;  cols[2] = j0 + 1;  cols[3] = j0 + 2;  cols[4] = j0 + 3;
        cols[5] = (j0 + 4 < WW) ? j0 + 4 : WW - 1;

#pragma unroll
        for (int t = 0; t < 6; t++) {
            V4 am = ldv(X + ((rowm + cols[t]) * C4 + c4));
            V4 a0 = ldv(X + ((row0 + cols[t]) * C4 + c4));
            V4 ap = ldv(X + ((rowp + cols[t]) * C4 + c4));
            vp[t] = mix4p(am, a0);
            vq[t] = mix4p(ap, a0);
        }
    }

#pragma unroll
    for (int jj = 0; jj < 4; jj++) {
        const int t = jj + 1;
        V4 u00 = mix4p(vp[t - 1], vp[t]);
        V4 u01 = mix4p(vp[t + 1], vp[t]);
        V4 u10 = mix4p(vq[t - 1], vq[t]);
        V4 u11 = mix4p(vq[t + 1], vq[t]);

        ulonglong2 s;
        s.x = sum4s(u00.a, u01.a, u10.a, u11.a);
        s.y = sum4s(u00.b, u01.b, u10.b, u11.b);
        obase[jj * C4] = s;
    }
}

extern "C" void kernel_launch(void* const* d_in, const int* in_sizes, int n_in,
                              void* d_out, int out_size) {
    const ulonglong2* X = (const ulonglong2*)d_in[0];
    ulonglong2* O = (ulonglong2*)d_out;
    dim3 block(32, 4, 1);
    dim3 grid(WW / 16, HH, BATCH);  // 8, 128, 16
    act_filter_kernel<<<grid, block>>>(X, O);
}

// round 4
// speedup vs baseline: 1.0249x; 1.0006x over previous
#include <cuda_runtime.h>

typedef unsigned long long ull;

#define BATCH 16
#define HH 128
#define WW 128
#define C4 32            // 128 channels as 4-float groups
#define JCOLS 8          // output columns per thread

// ---- packed fp32x2 primitives (sm_103a) ----
__device__ __forceinline__ ull mulp(ull a, ull b) {
    ull r; asm("mul.rn.f32x2 %0, %1, %2;" : "=l"(r) : "l"(a), "l"(b)); return r;
}
__device__ __forceinline__ ull addp(ull a, ull b) {
    ull r; asm("add.rn.f32x2 %0, %1, %2;" : "=l"(r) : "l"(a), "l"(b)); return r;
}
__device__ __forceinline__ ull fmap(ull a, ull b, ull c) {
    ull r; asm("fma.rn.f32x2 %0, %1, %2, %3;" : "=l"(r) : "l"(a), "l"(b), "l"(c)); return r;
}
__device__ __forceinline__ ull pack2f(float x) {
    ull r; asm("mov.b64 %0, {%1, %1};" : "=l"(r) : "f"(x)); return r;
}
__device__ __forceinline__ ull absp(ull u) {
    return u & 0x7FFFFFFF7FFFFFFFULL;   // clears both sign bits (LOP3, alu pipe)
}

struct V4 { ull a, b; };  // 4 packed floats

// 0.25*x + 0.75*y
__device__ __forceinline__ V4 mix4p(const V4& x, const V4& y, ull w25, ull w75) {
    V4 r;
    r.a = fmap(x.a, w25, mulp(y.a, w75));
    r.b = fmap(x.b, w25, mulp(y.b, w75));
    return r;
}

__device__ __forceinline__ V4 ldv(const ulonglong2* __restrict__ p) {
    ulonglong2 v = *p;
    V4 r; r.a = v.x; r.b = v.y;
    return r;
}

// 0.25 * sum_k lrelu(u_k)  ==  0.12625*sum(u) + 0.12375*sum(|u|)
__device__ __forceinline__ ull blend(ull u00, ull u01, ull u10, ull u11, ull ca, ull cb) {
    ull sl = addp(addp(u00, u01), addp(u10, u11));
    ull sa = addp(addp(absp(u00), absp(u01)), addp(absp(u10), absp(u11)));
    return fmap(sl, ca, mulp(sa, cb));
}

// block = (32 c4-lanes, 4 col-groups) = 128 threads
// each thread: one c4 group, JCOLS=8 consecutive output columns, streaming window.
// grid = (W/(8*4)=4, H=128, B=16)
__global__ __launch_bounds__(128, 9)
void act_filter_kernel(const ulonglong2* __restrict__ X, ulonglong2* __restrict__ O) {
    const int c4 = threadIdx.x;                      // 0..31
    const int jg = blockIdx.x * 4 + threadIdx.y;     // 0..15
    const int j0 = jg * JCOLS;
    const int i  = blockIdx.y;
    const int b  = blockIdx.z;

    const ull w25 = pack2f(0.25f);
    const ull w75 = pack2f(0.75f);
    const ull ca  = pack2f(0.12625f);   // 0.505 * 0.25
    const ull cb  = pack2f(0.12375f);   // 0.495 * 0.25

    const int row0 = (b * HH + i) * WW;
    // vertical neighbor deltas (clamped at H edges), in ulonglong2 elements
    const int dm = (i > 0)      ? -WW * C4 : 0;
    const int dp = (i < HH - 1) ?  WW * C4 : 0;

    const ulonglong2* __restrict__ p0 = X + (size_t)row0 * C4 + c4;  // + col*C4
    ulonglong2* __restrict__ po = O + ((size_t)row0 + j0) * C4 + c4; // + jj*C4

    V4 vp[3], vq[3];

#pragma unroll
    for (int t = 0; t < JCOLS + 2; t++) {
        // source column j0-1+t, clamped (clamps only possibly active at t=0 / t=JCOLS+1)
        int col = j0 - 1 + t;
        if (t == 0)          col = (j0 > 0) ? col : 0;
        if (t == JCOLS + 1)  col = (col < WW) ? col : WW - 1;
        const int off = col * C4;

        V4 a0 = ldv(p0 + off);
        V4 am = ldv(p0 + off + dm);
        V4 ap = ldv(p0 + off + dp);

        const int s = t % 3;
        vp[s] = mix4p(am, a0, w25, w75);   // up-row 2i
        vq[s] = mix4p(ap, a0, w25, w75);   // up-row 2i+1

        if (t >= 2) {
            const int sA = (t - 2) % 3, sB = (t - 1) % 3, sC = s;
            // up-cols 2j and 2j+1 for output col j = j0 + t - 2
            V4 u00 = mix4p(vp[sA], vp[sB], w25, w75);
            V4 u01 = mix4p(vp[sC], vp[sB], w25, w75);
            V4 u10 = mix4p(vq[sA], vq[sB], w25, w75);
            V4 u11 = mix4p(vq[sC], vq[sB], w25, w75);

            ulonglong2 out;
            out.x = blend(u00.a, u01.a, u10.a, u11.a, ca, cb);
            out.y = blend(u00.b, u01.b, u10.b, u11.b, ca, cb);
            po[(t - 2) * C4] = out;
        }
    }
}

extern "C" void kernel_launch(void* const* d_in, const int* in_sizes, int n_in,
                              void* d_out, int out_size) {
    const ulonglong2* X = (const ulonglong2*)d_in[0];
    ulonglong2* O = (ulonglong2*)d_out;
    dim3 block(32, 4, 1);
    dim3 grid(WW / (JCOLS * 4), HH, BATCH);  // 4, 128, 16
    act_filter_kernel<<<grid, block>>>(X, O);
}

// round 5
// speedup vs baseline: 1.0322x; 1.0072x over previous
#include <cuda_runtime.h>

typedef unsigned long long ull;

#define BATCH 16
#define HH 128
#define WW 128
#define LANES 64         // 128 channels as 64 packed-f32x2 lanes
#define JCOLS 8          // output columns per thread

// ---- packed fp32x2 primitives (sm_103a) ----
__device__ __forceinline__ ull mulp(ull a, ull b) {
    ull r; asm("mul.rn.f32x2 %0, %1, %2;" : "=l"(r) : "l"(a), "l"(b)); return r;
}
__device__ __forceinline__ ull addp(ull a, ull b) {
    ull r; asm("add.rn.f32x2 %0, %1, %2;" : "=l"(r) : "l"(a), "l"(b)); return r;
}
__device__ __forceinline__ ull fmap(ull a, ull b, ull c) {
    ull r; asm("fma.rn.f32x2 %0, %1, %2, %3;" : "=l"(r) : "l"(a), "l"(b), "l"(c)); return r;
}
__device__ __forceinline__ ull pack2f(float x) {
    ull r; asm("mov.b64 %0, {%1, %1};" : "=l"(r) : "f"(x)); return r;
}
__device__ __forceinline__ ull absp(ull u) {
    return u & 0x7FFFFFFF7FFFFFFFULL;   // clear both sign bits (one LOP3)
}

// 0.25*x + 0.75*y  (one FMA + one MUL, packed)
__device__ __forceinline__ ull mixp(ull x, ull y, ull w25, ull w75) {
    return fmap(x, w25, mulp(y, w75));
}

// block = (64 lanes, 2 col-groups) = 128 threads
// each thread: one 2-channel lane, JCOLS=8 consecutive output columns.
// grid = (W/(8*2)=8, H=128, B=16)
__global__ __launch_bounds__(128)
void act_filter_kernel(const ull* __restrict__ X, ull* __restrict__ O) {
    const int lane = threadIdx.x;                    // 0..63
    const int jg = blockIdx.x * 2 + threadIdx.y;     // 0..15
    const int j0 = jg * JCOLS;
    const int i  = blockIdx.y;
    const int b  = blockIdx.z;

    const ull w25 = pack2f(0.25f);
    const ull w75 = pack2f(0.75f);
    const ull ca  = pack2f(0.12625f);   // 0.505 * 0.25  (lrelu(u)=0.505u+0.495|u|)
    const ull cb  = pack2f(0.12375f);   // 0.495 * 0.25

    const int row0 = (b * HH + i) * WW;
    const int dm = (i > 0)      ? -WW * LANES : 0;   // clamped vertical neighbors
    const int dp = (i < HH - 1) ?  WW * LANES : 0;

    const ull* __restrict__ p0 = X + (size_t)row0 * LANES + lane;       // + col*LANES
    ull* __restrict__ po = O + ((size_t)row0 + j0) * LANES + lane;      // + jj*LANES

    ull vp[3], vq[3];

#pragma unroll
    for (int t = 0; t < JCOLS + 2; t++) {
        // source column j0-1+t, clamps only possibly active at the two ends
        int col = j0 - 1 + t;
        if (t == 0)          col = (col > 0) ? col : 0;
        if (t == JCOLS + 1)  col = (col < WW) ? col : WW - 1;
        const int off = col * LANES;

        ull a0 = p0[off];
        ull am = p0[off + dm];
        ull ap = p0[off + dp];

        const int s = t % 3;
        vp[s] = mixp(am, a0, w25, w75);   // up-row 2i
        vq[s] = mixp(ap, a0, w25, w75);   // up-row 2i+1

        if (t >= 2) {
            const int sA = (t - 2) % 3, sB = (t - 1) % 3;
            // up-cols 2j, 2j+1 for output col j = j0 + t - 2
            ull u00 = mixp(vp[sA], vp[sB], w25, w75);
            ull u01 = mixp(vp[s],  vp[sB], w25, w75);
            ull u10 = mixp(vq[sA], vq[sB], w25, w75);
            ull u11 = mixp(vq[s],  vq[sB], w25, w75);

            // 0.25 * sum lrelu(u)  ==  ca*sum(u) + cb*sum(|u|)
            ull sl = addp(addp(u00, u01), addp(u10, u11));
            ull sa = addp(addp(absp(u00), absp(u01)), addp(absp(u10), absp(u11)));
            po[(t - 2) * LANES] = fmap(sl, ca, mulp(sa, cb));
        }
    }
}

extern "C" void kernel_launch(void* const* d_in, const int* in_sizes, int n_in,
                              void* d_out, int out_size) {
    const ull* X = (const ull*)d_in[0];
    ull* O = (ull*)d_out;
    dim3 block(LANES, 2, 1);
    dim3 grid(WW / (JCOLS * 2), HH, BATCH);  // 8, 128, 16
    act_filter_kernel<<<grid, block>>>(X, O);
}

// round 6
// speedup vs baseline: 1.0732x; 1.0397x over previous
#include <cuda_runtime.h>

typedef unsigned long long ull;

#define BATCH 16
#define HH 128
#define WW 128
#define LANES 64         // 128 channels as 64 packed-f32x2 lanes
#define JCOLS 8          // output columns per thread
#define ROWSTEP (WW * LANES)

// ---- packed fp32x2 primitives (sm_103a) ----
__device__ __forceinline__ ull mulp(ull a, ull b) {
    ull r; asm("mul.rn.f32x2 %0, %1, %2;" : "=l"(r) : "l"(a), "l"(b)); return r;
}
__device__ __forceinline__ ull addp(ull a, ull b) {
    ull r; asm("add.rn.f32x2 %0, %1, %2;" : "=l"(r) : "l"(a), "l"(b)); return r;
}
__device__ __forceinline__ ull fmap(ull a, ull b, ull c) {
    ull r; asm("fma.rn.f32x2 %0, %1, %2, %3;" : "=l"(r) : "l"(a), "l"(b), "l"(c)); return r;
}
__device__ __forceinline__ ull pack2f(float x) {
    ull r; asm("mov.b64 %0, {%1, %1};" : "=l"(r) : "f"(x)); return r;
}
__device__ __forceinline__ ull absp(ull u) {
    return u & 0x7FFFFFFF7FFFFFFFULL;   // clear both sign bits (one LOP3)
}
// 0.25*x + 0.75*y
__device__ __forceinline__ ull mixp(ull x, ull y, ull w25, ull w75) {
    return fmap(x, w25, mulp(y, w75));
}
// streaming (evict-first) 8B store
__device__ __forceinline__ void stcs8(ull* p, ull v) {
    asm volatile("st.global.cs.b64 [%0], %1;" :: "l"(p), "l"(v) : "memory");
}

// block = (64 lanes, 2 col-groups) = 128 threads
// each thread: one 2-channel lane, 2 output rows x JCOLS=8 output columns.
// grid = (8, H/2=64, B=16)
__global__ __launch_bounds__(128)
void act_filter_kernel(const ull* __restrict__ X, ull* __restrict__ O) {
    const int lane = threadIdx.x;                    // 0..63
    const int jg = blockIdx.x * 2 + threadIdx.y;     // 0..15
    const int j0 = jg * JCOLS;
    const int i0 = blockIdx.y * 2;                   // output rows i0, i0+1
    const int b  = blockIdx.z;

    const ull w25 = pack2f(0.25f);
    const ull w75 = pack2f(0.75f);
    const ull ca  = pack2f(0.12625f);   // 0.505 * 0.25  (lrelu = 0.505u + 0.495|u|)
    const ull cb  = pack2f(0.12375f);   // 0.495 * 0.25

    const int row0 = (b * HH + i0) * WW;
    // vertical neighbor offsets relative to row i0 (clamped at H edges)
    const int dm  = (i0 > 0)       ? -ROWSTEP     : 0;          // row i0-1
    const int dp  = ROWSTEP;                                    // row i0+1 (i0 <= 126)
    const int dp2 = (i0 + 2 < HH)  ?  2 * ROWSTEP : ROWSTEP;    // row i0+2 clamped

    const ull* __restrict__ p0 = X + (size_t)row0 * LANES + lane;       // + col*LANES
    ull* __restrict__ po = O + ((size_t)row0 + j0) * LANES + lane;      // + jj*LANES

    // vertical mixes, rotating 3-column window; A = out row i0, B = out row i0+1
    ull vpA[3], vqA[3], vpB[3], vqB[3];

#pragma unroll
    for (int t = 0; t < JCOLS + 2; t++) {
        int col = j0 - 1 + t;
        if (t == 0)          col = (col > 0) ? col : 0;
        if (t == JCOLS + 1)  col = (col < WW) ? col : WW - 1;
        const int off = col * LANES;

        ull xm = p0[off + dm];    // x[i0-1]
        ull x0 = p0[off];         // x[i0]
        ull x1 = p0[off + dp];    // x[i0+1]
        ull x2 = p0[off + dp2];   // x[i0+2]

        const int s = t % 3;
        vpA[s] = mixp(xm, x0, w25, w75);   // 0.25 x[i0-1] + 0.75 x[i0]
        vqA[s] = mixp(x1, x0, w25, w75);   // 0.75 x[i0]   + 0.25 x[i0+1]
        vpB[s] = mixp(x0, x1, w25, w75);   // 0.25 x[i0]   + 0.75 x[i0+1]
        vqB[s] = mixp(x2, x1, w25, w75);   // 0.75 x[i0+1] + 0.25 x[i0+2]

        if (t >= 2) {
            const int sA = (t - 2) % 3, sB = (t - 1) % 3;
            // ---- output row i0 ----
            {
                ull u00 = mixp(vpA[sA], vpA[sB], w25, w75);
                ull u01 = mixp(vpA[s],  vpA[sB], w25, w75);
                ull u10 = mixp(vqA[sA], vqA[sB], w25, w75);
                ull u11 = mixp(vqA[s],  vqA[sB], w25, w75);
                ull sl = addp(addp(u00, u01), addp(u10, u11));
                ull sa = addp(addp(absp(u00), absp(u01)), addp(absp(u10), absp(u11)));
                stcs8(po + (t - 2) * LANES, fmap(sl, ca, mulp(sa, cb)));
            }
            // ---- output row i0+1 ----
            {
                ull u00 = mixp(vpB[sA], vpB[sB], w25, w75);
                ull u01 = mixp(vpB[s],  vpB[sB], w25, w75);
                ull u10 = mixp(vqB[sA], vqB[sB], w25, w75);
                ull u11 = mixp(vqB[s],  vqB[sB], w25, w75);
                ull sl = addp(addp(u00, u01), addp(u10, u11));
                ull sa = addp(addp(absp(u00), absp(u01)), addp(absp(u10), absp(u11)));
                stcs8(po + ROWSTEP + (t - 2) * LANES, fmap(sl, ca, mulp(sa, cb)));
            }
        }
    }
}

extern "C" void kernel_launch(void* const* d_in, const int* in_sizes, int n_in,
                              void* d_out, int out_size) {
    const ull* X = (const ull*)d_in[0];
    ull* O = (ull*)d_out;
    dim3 block(LANES, 2, 1);
    dim3 grid(WW / (JCOLS * 2), HH / 2, BATCH);  // 8, 64, 16
    act_filter_kernel<<<grid, block>>>(X, O);
}

// round 7
// speedup vs baseline: 1.0793x; 1.0056x over previous
#include <cuda_runtime.h>

typedef unsigned long long ull;

#define BATCH 16
#define HH 128
#define WW 128
#define LANES 64         // 128 channels as 64 packed-f32x2 lanes
#define JCOLS 8          // output columns per thread
#define NROWS 4          // output rows per thread
#define ROWSTEP (WW * LANES)

// ---- packed fp32x2 primitives (sm_103a) ----
__device__ __forceinline__ ull mulp(ull a, ull b) {
    ull r; asm("mul.rn.f32x2 %0, %1, %2;" : "=l"(r) : "l"(a), "l"(b)); return r;
}
__device__ __forceinline__ ull addp(ull a, ull b) {
    ull r; asm("add.rn.f32x2 %0, %1, %2;" : "=l"(r) : "l"(a), "l"(b)); return r;
}
__device__ __forceinline__ ull fmap(ull a, ull b, ull c) {
    ull r; asm("fma.rn.f32x2 %0, %1, %2, %3;" : "=l"(r) : "l"(a), "l"(b), "l"(c)); return r;
}
__device__ __forceinline__ ull pack2f(float x) {
    ull r; asm("mov.b64 %0, {%1, %1};" : "=l"(r) : "f"(x)); return r;
}
__device__ __forceinline__ ull absp(ull u) {
    return u & 0x7FFFFFFF7FFFFFFFULL;   // clear both sign bits (one LOP3)
}
// 0.25*x + 0.75*y
__device__ __forceinline__ ull mixp(ull x, ull y, ull w25, ull w75) {
    return fmap(x, w25, mulp(y, w75));
}
// streaming (evict-first) 8B store
__device__ __forceinline__ void stcs8(ull* p, ull v) {
    asm volatile("st.global.cs.b64 [%0], %1;" :: "l"(p), "l"(v) : "memory");
}

// block = (64 lanes, 2 col-groups) = 128 threads
// each thread: one 2-channel lane, NROWS=4 output rows x JCOLS=8 output columns.
// grid = (8, H/4=32, B=16)
__global__ __launch_bounds__(128)
void act_filter_kernel(const ull* __restrict__ X, ull* __restrict__ O) {
    const int lane = threadIdx.x;                    // 0..63
    const int jg = blockIdx.x * 2 + threadIdx.y;     // 0..15
    const int j0 = jg * JCOLS;
    const int i0 = blockIdx.y * NROWS;               // output rows i0..i0+3
    const int b  = blockIdx.z;

    const ull w25 = pack2f(0.25f);
    const ull w75 = pack2f(0.75f);
    const ull ca  = pack2f(0.12625f);   // 0.505 * 0.25  (lrelu = 0.505u + 0.495|u|)
    const ull cb  = pack2f(0.12375f);   // 0.495 * 0.25

    const int row0 = (b * HH + i0) * WW;
    // input row offsets relative to row i0 (ull elements), clamped at H edges
    const int dm = (i0 > 0) ? -ROWSTEP : 0;                     // row i0-1
    const int d4 = (i0 + NROWS < HH) ? 4 * ROWSTEP : 3 * ROWSTEP;  // row i0+4 clamped

    const ull* __restrict__ p0 = X + (size_t)row0 * LANES + lane;       // + col*LANES
    ull* __restrict__ po = O + ((size_t)row0 + j0) * LANES + lane;      // + jj*LANES

    // vertical mixes: v[2*r] = vp (up-row 2i), v[2*r+1] = vq (up-row 2i+1),
    // for output rows r = 0..3; rotating 3-column window.
    ull v[2 * NROWS][3];

#pragma unroll
    for (int t = 0; t < JCOLS + 2; t++) {
        int col = j0 - 1 + t;
        if (t == 0)          col = (col > 0) ? col : 0;
        if (t == JCOLS + 1)  col = (col < WW) ? col : WW - 1;
        const int off = col * LANES;

        // 6 input rows for this column (independent loads -> MLP 6)
        ull xm = p0[off + dm];
        ull x0 = p0[off];
        ull x1 = p0[off + ROWSTEP];
        ull x2 = p0[off + 2 * ROWSTEP];
        ull x3 = p0[off + 3 * ROWSTEP];
        ull x4 = p0[off + d4];

        const int s = t % 3;
        v[0][s] = mixp(xm, x0, w25, w75);   // row 0: vp
        v[1][s] = mixp(x1, x0, w25, w75);   // row 0: vq
        v[2][s] = mixp(x0, x1, w25, w75);   // row 1: vp
        v[3][s] = mixp(x2, x1, w25, w75);   // row 1: vq
        v[4][s] = mixp(x1, x2, w25, w75);   // row 2: vp
        v[5][s] = mixp(x3, x2, w25, w75);   // row 2: vq
        v[6][s] = mixp(x2, x3, w25, w75);   // row 3: vp
        v[7][s] = mixp(x4, x3, w25, w75);   // row 3: vq

        if (t >= 2) {
            const int sA = (t - 2) % 3, sB = (t - 1) % 3;
#pragma unroll
            for (int r = 0; r < NROWS; r++) {
                ull u00 = mixp(v[2*r][sA],   v[2*r][sB],   w25, w75);
                ull u01 = mixp(v[2*r][s],    v[2*r][sB],   w25, w75);
                ull u10 = mixp(v[2*r+1][sA], v[2*r+1][sB], w25, w75);
                ull u11 = mixp(v[2*r+1][s],  v[2*r+1][sB], w25, w75);
                // 0.25 * sum lrelu(u) == ca*sum(u) + cb*sum(|u|)
                ull sl = addp(addp(u00, u01), addp(u10, u11));
                ull sa = addp(addp(absp(u00), absp(u01)), addp(absp(u10), absp(u11)));
                stcs8(po + r * ROWSTEP + (t - 2) * LANES, fmap(sl, ca, mulp(sa, cb)));
            }
        }
    }
}

extern "C" void kernel_launch(void* const* d_in, const int* in_sizes, int n_in,
                              void* d_out, int out_size) {
    const ull* X = (const ull*)d_in[0];
    ull* O = (ull*)d_out;
    dim3 block(LANES, 2, 1);
    dim3 grid(WW / (JCOLS * 2), HH / NROWS, BATCH);  // 8, 32, 16
    act_filter_kernel<<<grid, block>>>(X, O);
}